// round 1
// baseline (speedup 1.0000x reference)
#include <cuda_runtime.h>
#include <math.h>

#define NFFT  2048
#define LOG2N 11
#define TPB   256
#define EPT   (NFFT / TPB)        // 8 elements per thread
#define BPT   (NFFT / 2 / TPB)    // 4 butterflies per thread
#define MAXB  64
#define NS    81                  // number of scales (J=80 -> 81)
#define WSZ   94                  // sliding window = 32*3 - 2
#define NOUT  (NFFT - WSZ + 1)    // 1955

#define PI_F  3.14159265358979323846f
#define TWO_PI_F 6.28318530717958647692f

// ---------------- scratch (static device globals; no runtime alloc) ----------
__device__ float2 g_yh[MAXB * 2 * NFFT];          // forward FFT of normalized inputs
__device__ float  g_T1[MAXB * NS * NFFT];         // smooth(|W1|^2/s)
__device__ float  g_T2[MAXB * NS * NFFT];         // smooth(|W2|^2/s)
__device__ float2 g_T12[MAXB * NS * NFFT];        // smooth(W1*conj(W2)/s)
__device__ float  g_coh[MAXB * NFFT];             // coherence summed over scales

// ---------------- shared-memory Stockham radix-2 FFT, N = 2048 ----------------
// input in sA (caller must __syncthreads() after filling), output in sB
// (11 stages = odd number of ping-pongs). No 1/N scaling applied.
__device__ __noinline__ void fft2048(float2* sA, float2* sB, const float2* __restrict__ tw,
                                     int tid, bool inverse) {
  float2* src = sA;
  float2* dst = sB;
  int mul = 1;
  #pragma unroll
  for (int ls = 0; ls < LOG2N; ++ls) {
    const int s = 1 << ls;
    #pragma unroll
    for (int r = 0; r < BPT; ++r) {
      int t = tid + r * TPB;       // butterfly id in [0, N/2)
      int p = t >> ls;
      int q = t & (s - 1);
      float2 w = tw[p * mul];      // e^{-2*pi*i * (p*mul) / N}
      float wy = inverse ? -w.y : w.y;
      int iu = q + s * p;
      float2 u = src[iu];
      float2 v = src[iu + (NFFT / 2)];
      int io = iu + s * p;
      dst[io] = make_float2(u.x + v.x, u.y + v.y);
      float dx = u.x - v.x, dy = u.y - v.y;
      dst[io + s] = make_float2(dx * w.x - dy * wy, dx * wy + dy * w.x);
    }
    __syncthreads();
    float2* tp = src; src = dst; dst = tp;
    mul <<= 1;
  }
}

__device__ __forceinline__ void build_tw(float2* tw, int tid) {
  #pragma unroll
  for (int r = 0; r < BPT; ++r) {
    int j = tid + r * TPB;
    float sv, cv;
    sincosf(-PI_F * (float)j * (1.0f / 1024.0f), &sv, &cv);
    tw[j] = make_float2(cv, sv);
  }
}

// ---------------- K1: normalize + forward FFT of each input signal ------------
__global__ void kern_fft_input(const float* __restrict__ x) {
  __shared__ float2 sA[NFFT];
  __shared__ float2 sB[NFFT];
  __shared__ float2 tw[NFFT / 2];
  __shared__ float  red[TPB];
  const int bc  = blockIdx.x;   // b*2 + channel
  const int tid = threadIdx.x;

  build_tw(tw, tid);

  const float* y = x + (size_t)bc * NFFT;
  float vals[EPT];
  float sum = 0.f, sumsq = 0.f;
  #pragma unroll
  for (int r = 0; r < EPT; ++r) {
    float v = y[tid + r * TPB];
    vals[r] = v;
    sum += v;
    sumsq += v * v;
  }
  // block reductions
  red[tid] = sum; __syncthreads();
  for (int o = TPB / 2; o > 0; o >>= 1) { if (tid < o) red[tid] += red[tid + o]; __syncthreads(); }
  float mean = red[0] * (1.0f / NFFT);
  __syncthreads();
  red[tid] = sumsq; __syncthreads();
  for (int o = TPB / 2; o > 0; o >>= 1) { if (tid < o) red[tid] += red[tid + o]; __syncthreads(); }
  float var = red[0] * (1.0f / NFFT) - mean * mean;
  float istd = rsqrtf(var);
  __syncthreads();

  #pragma unroll
  for (int r = 0; r < EPT; ++r)
    sA[tid + r * TPB] = make_float2((vals[r] - mean) * istd, 0.f);
  __syncthreads();

  fft2048(sA, sB, tw, tid, false);      // forward FFT, result in sB

  #pragma unroll
  for (int r = 0; r < EPT; ++r) {
    int k = tid + r * TPB;
    g_yh[(size_t)bc * NFFT + k] = sB[k];
  }
}

// ---------------- K2: per (batch, scale) CWT + time smoothing -----------------
__global__ void kern_scale() {
  __shared__ float2 sA[NFFT];
  __shared__ float2 sB[NFFT];
  __shared__ float2 tw[NFFT / 2];
  const int si  = blockIdx.x;   // scale index
  const int b   = blockIdx.y;   // batch
  const int tid = threadIdx.x;

  build_tw(tw, tid);

  // scale value (computed in double to match numpy float64 -> float32 cast)
  const double s0d = 2.0 * 0.1 * (6.0 + sqrt(38.0)) / (4.0 * 3.14159265358979323846);
  const float  sc    = (float)(s0d * exp2(0.125 * (double)si));
  const float  inv_s = 1.0f / sc;
  const float  norm  = sqrtf(TWO_PI_F * sc * 10.0f) * 0.75112554446494248f;  // sqrt(2*pi*s/dt)*pi^-.25
  const float  sdt   = sc * 10.0f;        // s / dt
  const float  INVN  = 1.0f / (float)NFFT;

  float2 w1[EPT], w2[EPT];

  // --- W1, W2: ifft( yh * norm * psi_hat ) ; psi_hat nonzero for k in [1,1023]
  #pragma unroll
  for (int c = 0; c < 2; ++c) {
    #pragma unroll
    for (int r = 0; r < EPT; ++r) {
      int k = tid + r * TPB;
      float2 v = make_float2(0.f, 0.f);
      if (k >= 1 && k < NFFT / 2) {
        float w = TWO_PI_F * (float)k * (1.0f / 204.8f);   // 2*pi*fftfreq(2048, 0.1)
        float d = sc * w - 6.0f;
        float g = norm * expf(-0.5f * d * d);
        float2 yh = g_yh[(size_t)(b * 2 + c) * NFFT + k];
        v = make_float2(yh.x * g, yh.y * g);
      }
      sA[k] = v;
    }
    __syncthreads();
    fft2048(sA, sB, tw, tid, true);
    #pragma unroll
    for (int r = 0; r < EPT; ++r) {
      int k = tid + r * TPB;
      float2 v = sB[k];
      if (c == 0) w1[r] = make_float2(v.x * INVN, v.y * INVN);
      else        w2[r] = make_float2(v.x * INVN, v.y * INVN);
    }
    __syncthreads();
  }

  const size_t base = ((size_t)b * NS + si) * NFFT;

  // --- packed power smoothing: P = |W1|^2/s + i*|W2|^2/s
  // F(k) is real and even => smoothing separates exactly into (T1, T2)
  #pragma unroll
  for (int r = 0; r < EPT; ++r) {
    int k = tid + r * TPB;
    float2 a = w1[r], bb = w2[r];
    sA[k] = make_float2((a.x * a.x + a.y * a.y) * inv_s,
                        (bb.x * bb.x + bb.y * bb.y) * inv_s);
  }
  __syncthreads();
  fft2048(sA, sB, tw, tid, false);
  #pragma unroll
  for (int r = 0; r < EPT; ++r) {
    int k = tid + r * TPB;
    float fk = (float)(k < NFFT / 2 ? k : k - NFFT) * (1.0f / NFFT);
    float kk = TWO_PI_F * fk;
    float F = expf(-0.5f * sdt * sdt * kk * kk);
    float2 v = sB[k];
    sA[k] = make_float2(v.x * F, v.y * F);
  }
  __syncthreads();
  fft2048(sA, sB, tw, tid, true);
  #pragma unroll
  for (int r = 0; r < EPT; ++r) {
    int k = tid + r * TPB;
    float2 v = sB[k];
    g_T1[base + k] = v.x * INVN;
    g_T2[base + k] = v.y * INVN;
  }
  __syncthreads();

  // --- cross spectrum smoothing: C = W1*conj(W2)/s (complex)
  #pragma unroll
  for (int r = 0; r < EPT; ++r) {
    int k = tid + r * TPB;
    float2 a = w1[r], bb = w2[r];
    sA[k] = make_float2((a.x * bb.x + a.y * bb.y) * inv_s,
                        (a.y * bb.x - a.x * bb.y) * inv_s);
  }
  __syncthreads();
  fft2048(sA, sB, tw, tid, false);
  #pragma unroll
  for (int r = 0; r < EPT; ++r) {
    int k = tid + r * TPB;
    float fk = (float)(k < NFFT / 2 ? k : k - NFFT) * (1.0f / NFFT);
    float kk = TWO_PI_F * fk;
    float F = expf(-0.5f * sdt * sdt * kk * kk);
    float2 v = sB[k];
    sA[k] = make_float2(v.x * F, v.y * F);
  }
  __syncthreads();
  fft2048(sA, sB, tw, tid, true);
  #pragma unroll
  for (int r = 0; r < EPT; ++r) {
    int k = tid + r * TPB;
    float2 v = sB[k];
    g_T12[base + k] = make_float2(v.x * INVN, v.y * INVN);
  }
}

// ---------------- K3: scale smoothing + coherence + sum over scales -----------
// jnp.convolve(col, win, 'same'), win = [.5,1,...,1,.5]/9 (len 10):
// S_sm[i] = (1/9) * sum_{j=i-5..i+4, clipped} w(j)*col[j], w = 0.5 at j=i-5, i+4.
// The 1/9 cancels in |S12|^2/(S1*S2), so it is omitted.
__global__ void kern_coh() {
  const int b = blockIdx.y;
  const int t = blockIdx.x * TPB + threadIdx.x;
  const size_t bb = (size_t)b * NS * NFFT + t;
  float acc = 0.f;
  for (int i = 0; i < NS; ++i) {
    float s1 = 0.f, s2 = 0.f, cr = 0.f, ci = 0.f;
    int j0 = i - 5 < 0 ? 0 : i - 5;
    int j1 = i + 4 >= NS ? NS - 1 : i + 4;
    for (int j = j0; j <= j1; ++j) {
      float wgt = (j == i - 5 || j == i + 4) ? 0.5f : 1.0f;
      size_t off = bb + (size_t)j * NFFT;
      s1 += wgt * __ldg(&g_T1[off]);
      s2 += wgt * __ldg(&g_T2[off]);
      float2 c = __ldg(&g_T12[off]);
      cr += wgt * c.x;
      ci += wgt * c.y;
    }
    acc += (cr * cr + ci * ci) / (s1 * s2);
  }
  g_coh[(size_t)b * NFFT + t] = acc;
}

// ---------------- K4: sliding window sum (WSZ=94) ------------------------------
__global__ void kern_slide(float* __restrict__ out) {
  __shared__ float sc[NFFT];
  const int b = blockIdx.x;
  const int tid = threadIdx.x;
  #pragma unroll
  for (int r = 0; r < EPT; ++r)
    sc[tid + r * TPB] = g_coh[(size_t)b * NFFT + tid + r * TPB];
  __syncthreads();
  for (int i = tid; i < NOUT; i += TPB) {
    float s = 0.f;
    for (int k = 0; k < WSZ; ++k) s += sc[i + k];
    out[(size_t)b * NOUT + i] = s;
  }
}

// ---------------- launch -------------------------------------------------------
extern "C" void kernel_launch(void* const* d_in, const int* in_sizes, int n_in,
                              void* d_out, int out_size) {
  const float* x = (const float*)d_in[0];
  int B = in_sizes[0] / (2 * NFFT);
  if (B > MAXB) B = MAXB;
  if (B <= 0) return;

  kern_fft_input<<<B * 2, TPB>>>(x);
  kern_scale<<<dim3(NS, B), TPB>>>();
  kern_coh<<<dim3(NFFT / TPB, B), TPB>>>();
  kern_slide<<<B, TPB>>>((float*)d_out);
}